// round 17
// baseline (speedup 1.0000x reference)
#include <cuda_runtime.h>
#include <cuda_fp16.h>
#include <cstdint>

#define NTHREADS 384
#define NW 12

// ---- smem layout ----
#define XSTR 136                        // W2 row stride (fp16 elems), permuted-k
#define ASTR 72                         // Wf row stride
#define O_W2H 0
#define O_WFH (32 * XSTR)
#define SM_ELEMS (O_WFH + 128 * ASTR)   // 13568 fp16
#define O_BIAS (SM_ELEMS * 2)           // byte off: b2[32]f32 then bf[128]f32
#define O_STAGE 28672                   // 1KB-aligned; stages: 12 warps x 2 x 8KB
#define STAGE_BYTES 8192
#define O_SCR (O_STAGE + NW * 2 * STAGE_BYTES)
#define SM_BYTES (O_SCR + NW * 64 * 4)  // ~228KB

typedef unsigned u32;

static __device__ __forceinline__ u32 s2u(const void* p) {
    u32 a;
    asm("{ .reg .u64 t; cvta.to.shared.u64 t, %1; cvt.u32.u64 %0, t; }" : "=r"(a) : "l"(p));
    return a;
}
static __device__ __forceinline__ u32 packh(float a, float b) {
    __half2 hh = __floats2half2_rn(a, b);
    return *reinterpret_cast<u32*>(&hh);
}
static __device__ __forceinline__ void ldmx4(u32 a[4], u32 addr) {
    asm volatile("ldmatrix.sync.aligned.m8n8.x4.shared.b16 {%0,%1,%2,%3}, [%4];"
                 : "=r"(a[0]), "=r"(a[1]), "=r"(a[2]), "=r"(a[3]) : "r"(addr));
}
static __device__ __forceinline__ float4 lds128(u32 addr) {
    float4 v;
    asm volatile("ld.shared.v4.f32 {%0,%1,%2,%3}, [%4];"
                 : "=f"(v.x), "=f"(v.y), "=f"(v.z), "=f"(v.w) : "r"(addr));
    return v;
}
static __device__ __forceinline__ void cp16(u32 dst, const void* src) {
    asm volatile("cp.async.cg.shared.global [%0], [%1], 16;" :: "r"(dst), "l"(src) : "memory");
}
#define CP_COMMIT() asm volatile("cp.async.commit_group;" ::: "memory")
#define CP_WAIT1()  asm volatile("cp.async.wait_group 1;"  ::: "memory")
#define CP_WAIT0()  asm volatile("cp.async.wait_group 0;"  ::: "memory")

static __device__ __forceinline__ void mmaf16(float c[4], const u32 a[4], u32 b0, u32 b1) {
    asm volatile("mma.sync.aligned.m16n8k16.row.col.f32.f16.f16.f32 "
                 "{%0,%1,%2,%3}, {%4,%5,%6,%7}, {%8,%9}, {%0,%1,%2,%3};"
                 : "+f"(c[0]), "+f"(c[1]), "+f"(c[2]), "+f"(c[3])
                 : "r"(a[0]), "r"(a[1]), "r"(a[2]), "r"(a[3]), "r"(b0), "r"(b1));
}

__global__ void __launch_bounds__(NTHREADS, 1)
dynlayer_mma(const float* __restrict__ X,  const float* __restrict__ W1,
             const float* __restrict__ b1, const float* __restrict__ W2,
             const float* __restrict__ b2, const float* __restrict__ Wf,
             const float* __restrict__ bf, float* __restrict__ out, int nrows)
{
    extern __shared__ char smraw[];
    __half* sh = (__half*)smraw;
    float* b2s = (float*)(smraw + O_BIAS);
    float* bfs = b2s + 32;
    float* scr = (float*)(smraw + O_SCR);
    const u32 sb = s2u(smraw);
    const int tid = threadIdx.x, wid = tid >> 5, lane = tid & 31;

    // ---- stage weights + biases (W2 k-permuted as in R13) ----
    for (int i = tid; i < 32 * 128; i += NTHREADS) {
        int u = i >> 7, k = i & 127;
        int kb = k >> 4, p = k & 15, j = p >> 2, r = p & 3;
        int l = (r < 2) ? (2 * j + r) : (2 * j + 8 + r - 2);
        sh[O_W2H + u * XSTR + kb * 16 + l] = __float2half_rn(W2[i]);
    }
    for (int i = tid; i < 128 * 64; i += NTHREADS) {
        int n = i >> 6, k = i & 63;
        sh[O_WFH + n * ASTR + k] = __float2half_rn(Wf[i]);
    }
    if (tid < 32)  b2s[tid] = b2[tid];
    if (tid < 128) bfs[tid] = bf[tid];
    __syncthreads();

    const int q  = lane >> 2;          // row-in-group 0..7
    const int c2 = (lane & 3) * 2;     // out-col pair base

    const int brow  = ((lane >> 4) & 1) * 8 + (lane & 7);
    const int bcolh = ((lane >> 3) & 1) * 8;
    const u32 w2h = sb + (u32)((O_W2H + brow * XSTR + bcolh) * 2);
    const u32 wfh = sb + (u32)((O_WFH + brow * ASTR + bcolh) * 2);

    float2 b2c[4];
    #pragma unroll
    for (int nb = 0; nb < 4; nb++)
        b2c[nb] = *reinterpret_cast<const float2*>(b2s + nb * 8 + c2);

    const u32 stage0 = sb + O_STAGE + (u32)(wid * 2) * STAGE_BYTES;
    const u32 xoffA = (u32)(q * 512 + (lane & 3) * 16);
    const u32 hx64  = (u32)((q & 1) * 64);          // XOR term for this lane's rows

    const int NT = nrows >> 4;                      // 16-row warp-tiles
    const int GW = gridDim.x * NW;
    const int gw0 = blockIdx.x * NW + wid;

    auto stage_load = [&](int buf, int tile) {
        const u32 sbase = stage0 + (u32)buf * STAGE_BYTES;
        const float* src = X + (long)tile * 16 * 128 + lane * 4;
        #pragma unroll
        for (int j = 0; j < 16; j++)
            cp16(sbase + (u32)(j * 512) + (((u32)lane * 16) ^ ((u32)(j & 1) * 64)),
                 src + j * 128);
    };

    // ---- prologue: two stages in flight ----
    if (gw0 < NT) stage_load(0, gw0);
    CP_COMMIT();
    if (gw0 + GW < NT) stage_load(1, gw0 + GW);
    CP_COMMIT();

    int buf = 0;
    for (int t = gw0; t < NT; t += GW, buf ^= 1) {
        // L2 prefetch 3 tiles ahead (8KB slab, 2 lines/lane)
        if (t + 3 * GW < NT) {
            const char* p = (const char*)(X + (long)(t + 3 * GW) * 16 * 128) + lane * 256;
            asm volatile("prefetch.global.L2 [%0];" :: "l"(p));
            asm volatile("prefetch.global.L2 [%0];" :: "l"(p + 128));
        }

        CP_WAIT1();
        __syncwarp();
        const u32 xb0 = stage0 + (u32)buf * STAGE_BYTES + xoffA;
        const u32 xb1 = xb0 + 8 * 512;
        const long rw = (long)t * 16;

        float s1 = 0.f, s2 = 0.f;
        float accA[4][4];
        #pragma unroll
        for (int nb = 0; nb < 4; nb++)
            #pragma unroll
            for (int j = 0; j < 4; j++) accA[nb][j] = 0.f;

        // ---- GEMM1: o2 = xh @ W2h^T (M=16,N=32,K=128); hi-term only ----
        #pragma unroll
        for (int half = 0; half < 2; half++) {
            float4 xq[4], xp[4];
            #pragma unroll
            for (int kb = 0; kb < 4; kb++) {
                const u32 off = ((u32)((half * 4 + kb) * 64)) ^ hx64;
                xq[kb] = lds128(xb0 + off);
                xp[kb] = lds128(xb1 + off);
            }
            #pragma unroll
            for (int kb = 0; kb < 4; kb++) {
                s1 += fabsf(xq[kb].x) + fabsf(xq[kb].y) + fabsf(xq[kb].z) + fabsf(xq[kb].w);
                s2 += fabsf(xp[kb].x) + fabsf(xp[kb].y) + fabsf(xp[kb].z) + fabsf(xp[kb].w);
            }
            #pragma unroll
            for (int kb = 0; kb < 4; kb++) {
                u32 ah[4];
                ah[0] = packh(xq[kb].x, xq[kb].y);
                ah[1] = packh(xp[kb].x, xp[kb].y);
                ah[2] = packh(xq[kb].z, xq[kb].w);
                ah[3] = packh(xp[kb].z, xp[kb].w);
                const int kg = half * 4 + kb;
                #pragma unroll
                for (int nbp = 0; nbp < 2; nbp++) {
                    const u32 off = (u32)((nbp * 16 * XSTR + kg * 16) * 2);
                    u32 bh[4];
                    ldmx4(bh, w2h + off);
                    mmaf16(accA[2*nbp],   ah, bh[0], bh[1]);
                    mmaf16(accA[2*nbp+1], ah, bh[2], bh[3]);
                }
            }
        }
        __syncwarp();   // all lanes done reading this stage
        if (t + 2 * GW < NT) stage_load(buf, t + 2 * GW);
        CP_COMMIT();    // always commit to keep group accounting

        // ---- mask: quad-reduce per-row sum|x| (exact fp32 — untouchable) ----
        s1 += __shfl_xor_sync(0xffffffffu, s1, 1); s1 += __shfl_xor_sync(0xffffffffu, s1, 2);
        s2 += __shfl_xor_sync(0xffffffffu, s2, 1); s2 += __shfl_xor_sync(0xffffffffu, s2, 2);
        const bool mr1 = s1 > 128.0f, mr2 = s2 > 128.0f;      // sum>128 <=> mean|x|>1
        const u32 bal1 = __ballot_sync(0xffffffffu, mr1);
        const u32 bal2 = __ballot_sync(0xffffffffu, mr2);

        // ---- epilogue1 in regs: bias+relu -> GEMM2 A-fragments (hi only) ----
        u32 A2h[2][4];
        #pragma unroll
        for (int nb = 0; nb < 4; nb++) {
            float v0 = fmaxf(accA[nb][0] + b2c[nb].x, 0.f);
            float v1 = fmaxf(accA[nb][1] + b2c[nb].y, 0.f);
            float v2 = fmaxf(accA[nb][2] + b2c[nb].x, 0.f);
            float v3 = fmaxf(accA[nb][3] + b2c[nb].y, 0.f);
            const int kb2 = nb >> 1, base = (nb & 1) * 2;     // C layout == A layout
            A2h[kb2][base + 0] = packh(v0, v1);
            A2h[kb2][base + 1] = packh(v2, v3);
        }

        // ---- GEMM2: out = o2 @ Wf^T (M=16,N=128,K=32), nh-split ----
        const long row1 = rw + q, row2 = rw + q + 8;
        #pragma unroll
        for (int nh = 0; nh < 2; nh++) {
            float acc2[8][4];
            #pragma unroll
            for (int nb = 0; nb < 8; nb++)
                #pragma unroll
                for (int j = 0; j < 4; j++) acc2[nb][j] = 0.f;
            #pragma unroll
            for (int kb2 = 0; kb2 < 2; kb2++)
                #pragma unroll
                for (int nbp = 0; nbp < 4; nbp++) {
                    const u32 off = (u32)(((nh * 64 + nbp * 16) * ASTR + kb2 * 16) * 2);
                    u32 bh4[4];
                    ldmx4(bh4, wfh + off);
                    mmaf16(acc2[2*nbp],   A2h[kb2], bh4[0], bh4[1]);
                    mmaf16(acc2[2*nbp+1], A2h[kb2], bh4[2], bh4[3]);
                }
            #pragma unroll
            for (int nb = 0; nb < 8; nb++) {
                const int col = nh * 64 + nb * 8 + c2;
                const float2 bv = *reinterpret_cast<const float2*>(bfs + col);
                if (!mr1)
                    *reinterpret_cast<float2*>(out + row1 * 128 + col) =
                        make_float2(acc2[nb][0] + bv.x, acc2[nb][1] + bv.y);
                if (!mr2)
                    *reinterpret_cast<float2*>(out + row2 * 128 + col) =
                        make_float2(acc2[nb][2] + bv.x, acc2[nb][3] + bv.y);
            }
        }

        // ---- rare slow path: masked rows computed fully in fp32 from global ----
        if (bal1 | bal2) {
            float* o1s = scr + wid * 64;
            for (int r = 0; r < 16; r++) {
                const bool masked = (r < 8) ? ((bal1 >> (4 * r)) & 1u)
                                            : ((bal2 >> (4 * (r - 8))) & 1u);
                if (!masked) continue;
                const float4* xg4 = reinterpret_cast<const float4*>(X + (rw + r) * 128);
                #pragma unroll
                for (int uu = 0; uu < 2; uu++) {
                    const int u = lane + uu * 32;
                    const float4* wr = reinterpret_cast<const float4*>(W1 + u * 128);
                    float sacc = 0.f;
                    for (int k = 0; k < 32; k++) {
                        float4 a = xg4[k], w = wr[k];
                        sacc += a.x * w.x + a.y * w.y + a.z * w.z + a.w * w.w;
                    }
                    o1s[u] = fmaxf(sacc + b1[u], 0.f);
                }
                __syncwarp();
                #pragma unroll
                for (int jj = 0; jj < 4; jj++) {
                    const int d = lane + jj * 32;
                    const float* wf = Wf + d * 64;
                    float acc = bfs[d];
                    for (int u = 0; u < 64; u++) acc += o1s[u] * wf[u];
                    out[(rw + r) * 128 + d] = acc;
                }
                __syncwarp();
            }
        }
    }
    CP_WAIT0();
}

extern "C" void kernel_launch(void* const* d_in, const int* in_sizes, int n_in,
                              void* d_out, int out_size)
{
    const float* X  = (const float*)d_in[0];
    const float* W1 = (const float*)d_in[1];
    const float* b1 = (const float*)d_in[2];
    const float* W2 = (const float*)d_in[3];
    const float* b2 = (const float*)d_in[4];
    const float* Wf = (const float*)d_in[5];
    const float* bf = (const float*)d_in[6];
    float* out = (float*)d_out;

    const int nrows = in_sizes[0] / 128;

    cudaFuncSetAttribute(dynlayer_mma,
                         cudaFuncAttributeMaxDynamicSharedMemorySize, SM_BYTES);
    int nsm = 148;
    cudaDeviceGetAttribute(&nsm, cudaDevAttrMultiProcessorCount, 0);

    dynlayer_mma<<<nsm, NTHREADS, SM_BYTES>>>(X, W1, b1, W2, b2, Wf, bf, out, nrows);
}